// round 7
// baseline (speedup 1.0000x reference)
#include <cuda_runtime.h>
#include <cstdint>

// CIN_52553219834054 — per-(batch,d) bilinear 2-layer MLP + pooled FC, as tf32 tensor-core GEMM.
// B=1024, F=64, D=64. Inputs: x(1024,64,64) W1(64,4096) b1(64) W2(64,4096) b2(64) Wfc(1,128) bfc(1).
// out[b] = sum_d sum_o h1[o,d]*Wfc[o] + h2[o,d]*Wfc[64+o], + bfc.
//
// Mapping: rows p = (batch_local*64 + d), 128 per CTA (2 batches). N=64 outputs. K=4096 = 64 i-chunks x 64 j.
// A[p, i*64+j] = X0[p,i] * H[p,j]  — H fragment cached in regs (chunk-invariant), scaled by X0 scalar.
// W chunk (64x64) double-buffered in smem as tf32, XOR-swizzled for conflict-free B-fragment LDS.

#define NTHREADS 128
#define SMEM_BYTES (( (128*65)*2 + 8192 + 256 + 2 )*4)

__device__ __forceinline__ unsigned f2tf(float x) {
    unsigned u;
    asm("cvt.rna.tf32.f32 %0, %1;" : "=r"(u) : "f"(x));
    return u;
}

// swizzled linear index into a 64x64 W tile stored row-major by j (row = j, col = o ^ s(j))
__device__ __forceinline__ int wswz(int o, int j) {
    return (j << 6) + (o ^ (((j & 3) << 3) ^ ((j >> 2) & 7)));
}

__device__ __forceinline__ void mma8(float& c0, float& c1, float& c2, float& c3,
                                     unsigned a0, unsigned a1, unsigned a2, unsigned a3,
                                     unsigned b0, unsigned b1) {
    asm volatile(
        "mma.sync.aligned.m16n8k8.row.col.f32.tf32.tf32.f32 "
        "{%0,%1,%2,%3}, {%4,%5,%6,%7}, {%8,%9}, {%0,%1,%2,%3};"
        : "+f"(c0), "+f"(c1), "+f"(c2), "+f"(c3)
        : "r"(a0), "r"(a1), "r"(a2), "r"(a3), "r"(b0), "r"(b1));
}

__global__ __launch_bounds__(NTHREADS, 2) void CIN_52553219834054_kernel(
    const float* __restrict__ x,
    const float* __restrict__ W1, const float* __restrict__ b1v,
    const float* __restrict__ W2, const float* __restrict__ b2v,
    const float* __restrict__ Wfc, const float* __restrict__ bfc,
    float* __restrict__ out)
{
    extern __shared__ float sm[];
    float* Hs  = sm;               // [128][65]
    float* X0s = Hs  + 128 * 65;   // [128][65]
    float* Wb  = X0s + 128 * 65;   // [2][64*64] tf32 bit patterns
    float* sb1 = Wb  + 8192;       // [64]
    float* sb2 = sb1 + 64;         // [64]
    float* swf = sb2 + 64;         // [128]
    float* red = swf + 128;        // [2]

    const int tid  = threadIdx.x;
    const int lane = tid & 31;
    const int w    = tid >> 5;     // warp 0..3
    const int g    = lane >> 2;    // 0..7
    const int t    = lane & 3;     // 0..3
    const int b0g  = blockIdx.x * 2;

    if (tid < 2)   red[tid] = 0.0f;
    if (tid < 64)  { sb1[tid] = b1v[tid]; sb2[tid] = b2v[tid]; }
    if (tid < 128) swf[tid] = Wfc[tid];

    // ---- Load x into Hs and X0s: Hs[bl*64+d][f] = x[b0g+bl][f][d] ----
    {
        const int f0 = tid >> 4;          // 0..7
        const int d0 = (tid & 15) * 4;    // 0..60
        for (int bl = 0; bl < 2; bl++) {
            const float* xb = x + (size_t)(b0g + bl) * 4096;
            #pragma unroll
            for (int fo = 0; fo < 8; fo++) {
                int f = f0 + fo * 8;
                float4 v = *(const float4*)(xb + f * 64 + d0);
                int r = bl * 64 + d0;
                Hs[(r + 0) * 65 + f] = v.x;  X0s[(r + 0) * 65 + f] = v.x;
                Hs[(r + 1) * 65 + f] = v.y;  X0s[(r + 1) * 65 + f] = v.y;
                Hs[(r + 2) * 65 + f] = v.z;  X0s[(r + 2) * 65 + f] = v.z;
                Hs[(r + 3) * 65 + f] = v.w;  X0s[(r + 3) * 65 + f] = v.w;
            }
        }
    }
    __syncthreads();

    const float* Wls[2] = { W1, W2 };
    const int o8 = (tid >> 4) * 8;       // staging: base output row
    const int js = (tid & 15) * 4;       // staging: base j

    float pool = 0.0f;

    for (int layer = 0; layer < 2; layer++) {
        const float* Wl = Wls[layer];

        // ---- hoist H fragments into regs (reused for all 64 i-chunks) ----
        float hA0[2][8], hA1[2][8], hB0[2][8], hB1[2][8];
        #pragma unroll
        for (int s = 0; s < 2; s++) {
            int rA = w * 32 + s * 16 + g;
            int rB = rA + 8;
            #pragma unroll
            for (int jc = 0; jc < 8; jc++) {
                hA0[s][jc] = Hs[rA * 65 + jc * 8 + t];
                hA1[s][jc] = Hs[rA * 65 + jc * 8 + t + 4];
                hB0[s][jc] = Hs[rB * 65 + jc * 8 + t];
                hB1[s][jc] = Hs[rB * 65 + jc * 8 + t + 4];
            }
        }

        float acc[2][8][4];
        #pragma unroll
        for (int s = 0; s < 2; s++)
            #pragma unroll
            for (int nt = 0; nt < 8; nt++)
                #pragma unroll
                for (int k = 0; k < 4; k++) acc[s][nt][k] = 0.0f;

        // ---- stage chunk 0 into buffer 0 ----
        {
            const float* src = Wl + 0 * 64;
            #pragma unroll
            for (int oo = 0; oo < 8; oo++) {
                int o = o8 + oo;
                float4 v = *(const float4*)(src + (size_t)o * 4096 + js);
                Wb[wswz(o, js + 0)] = __uint_as_float(f2tf(v.x));
                Wb[wswz(o, js + 1)] = __uint_as_float(f2tf(v.y));
                Wb[wswz(o, js + 2)] = __uint_as_float(f2tf(v.z));
                Wb[wswz(o, js + 3)] = __uint_as_float(f2tf(v.w));
            }
        }
        __syncthreads();

        for (int i = 0; i < 64; i++) {
            // prefetch next W chunk into regs
            float4 pf[8];
            if (i < 63) {
                const float* src = Wl + (i + 1) * 64;
                #pragma unroll
                for (int oo = 0; oo < 8; oo++) {
                    int o = o8 + oo;
                    pf[oo] = *(const float4*)(src + (size_t)o * 4096 + js);
                }
            }

            // x0 scalars for this i (broadcast LDS)
            float xa0 = X0s[(w * 32 +  0 + g) * 65 + i];
            float xb0 = X0s[(w * 32 +  8 + g) * 65 + i];
            float xa1 = X0s[(w * 32 + 16 + g) * 65 + i];
            float xb1 = X0s[(w * 32 + 24 + g) * 65 + i];

            const float* WB = Wb + (i & 1) * 4096;

            #pragma unroll
            for (int jc = 0; jc < 8; jc++) {
                // A fragments: a0=(rowA,k0) a1=(rowB,k0) a2=(rowA,k1) a3=(rowB,k1)
                unsigned s0a0 = f2tf(xa0 * hA0[0][jc]);
                unsigned s0a1 = f2tf(xb0 * hB0[0][jc]);
                unsigned s0a2 = f2tf(xa0 * hA1[0][jc]);
                unsigned s0a3 = f2tf(xb0 * hB1[0][jc]);
                unsigned s1a0 = f2tf(xa1 * hA0[1][jc]);
                unsigned s1a1 = f2tf(xb1 * hB0[1][jc]);
                unsigned s1a2 = f2tf(xa1 * hA1[1][jc]);
                unsigned s1a3 = f2tf(xb1 * hB1[1][jc]);
                int j0 = jc * 8 + t;
                int j1 = j0 + 4;
                #pragma unroll
                for (int nt = 0; nt < 8; nt++) {
                    int o = nt * 8 + g;
                    unsigned bb0 = __float_as_uint(WB[wswz(o, j0)]);
                    unsigned bb1 = __float_as_uint(WB[wswz(o, j1)]);
                    mma8(acc[0][nt][0], acc[0][nt][1], acc[0][nt][2], acc[0][nt][3],
                         s0a0, s0a1, s0a2, s0a3, bb0, bb1);
                    mma8(acc[1][nt][0], acc[1][nt][1], acc[1][nt][2], acc[1][nt][3],
                         s1a0, s1a1, s1a2, s1a3, bb0, bb1);
                }
            }

            // store prefetched chunk into the other buffer
            if (i < 63) {
                float* dst = Wb + ((i + 1) & 1) * 4096;
                #pragma unroll
                for (int oo = 0; oo < 8; oo++) {
                    int o = o8 + oo;
                    dst[wswz(o, js + 0)] = __uint_as_float(f2tf(pf[oo].x));
                    dst[wswz(o, js + 1)] = __uint_as_float(f2tf(pf[oo].y));
                    dst[wswz(o, js + 2)] = __uint_as_float(f2tf(pf[oo].z));
                    dst[wswz(o, js + 3)] = __uint_as_float(f2tf(pf[oo].w));
                }
            }
            __syncthreads();
        }

        // ---- epilogue: bias + relu, pooled FC accumulation, writeback for layer 2 ----
        const float* sbias = (layer == 0) ? sb1 : sb2;
        const float* wfcl  = swf + layer * 64;
        #pragma unroll
        for (int s = 0; s < 2; s++) {
            int rA = w * 32 + s * 16 + g;
            int rB = rA + 8;
            #pragma unroll
            for (int nt = 0; nt < 8; nt++) {
                int n0 = nt * 8 + 2 * t;
                int n1 = n0 + 1;
                float h00 = fmaxf(acc[s][nt][0] + sbias[n0], 0.0f);  // (rA, n0)
                float h01 = fmaxf(acc[s][nt][1] + sbias[n1], 0.0f);  // (rA, n1)
                float h10 = fmaxf(acc[s][nt][2] + sbias[n0], 0.0f);  // (rB, n0)
                float h11 = fmaxf(acc[s][nt][3] + sbias[n1], 0.0f);  // (rB, n1)
                pool += (h00 + h10) * wfcl[n0] + (h01 + h11) * wfcl[n1];
                if (layer == 0) {
                    Hs[rA * 65 + n0] = h00;  Hs[rA * 65 + n1] = h01;
                    Hs[rB * 65 + n0] = h10;  Hs[rB * 65 + n1] = h11;
                }
            }
        }
        __syncthreads();
    }

    // ---- reduce pooled partials: warps 0,1 -> batch 0; warps 2,3 -> batch 1 ----
    atomicAdd(&red[w >> 1], pool);
    __syncthreads();
    if (tid == 0) {
        float c = bfc[0];
        out[b0g + 0] = red[0] + c;
        out[b0g + 1] = red[1] + c;
    }
}

extern "C" void kernel_launch(void* const* d_in, const int* in_sizes, int n_in,
                              void* d_out, int out_size) {
    (void)in_sizes; (void)n_in; (void)out_size;
    const float* x   = (const float*)d_in[0];
    const float* W1  = (const float*)d_in[1];
    const float* b1v = (const float*)d_in[2];
    const float* W2  = (const float*)d_in[3];
    const float* b2v = (const float*)d_in[4];
    const float* Wfc = (const float*)d_in[5];
    const float* bfc = (const float*)d_in[6];
    float* out = (float*)d_out;

    cudaFuncSetAttribute(CIN_52553219834054_kernel,
                         cudaFuncAttributeMaxDynamicSharedMemorySize, SMEM_BYTES);
    CIN_52553219834054_kernel<<<512, NTHREADS, SMEM_BYTES>>>(
        x, W1, b1v, W2, b2v, Wfc, bfc, out);
}

// round 11
// speedup vs baseline: 1.8660x; 1.8660x over previous
#include <cuda_runtime.h>
#include <cuda_fp16.h>
#include <cstdint>

// CIN_52553219834054 — per-(batch,d) bilinear 2-layer MLP + pooled FC via fp16 mma.sync.m16n8k16.
// Rows p = (batch_local*64 + d), 128 per CTA (2 batches). N=64 outputs. K=4096 = 64 chunks of 64.
// A[p, i*64+j] = x0[p,i]*h[p,j] built in regs (h frag chunk-invariant, scaled by x0 scalar).
// W pre-converted to fp16 fragment-major pre-swizzled layout by prep kernel; cp.async 4-deep ring.

#define THREADS 128
#define HS_ST 72                      // Hs row stride in halves
#define SMEM_BYTES 69632

__device__ __align__(16) unsigned g_Wh[2 * 64 * 2048];   // 2 layers x 64 chunks x 8KB

// prep: fragment-major fp16 W. For (l, o, jp): jp -> i,ks,pair,t. Value pair W[o][jcol..+1].
// Placed at chunk-local swizzled byte (e*64 + f*4) ^ (((e*64+f*4)>>3)&0x70),
// e = ks*32 + t*8 + g, f = nt*2 + pair, o = nt*8+g.
__global__ void prep_kernel(const float* __restrict__ W1, const float* __restrict__ W2) {
    unsigned q = blockIdx.x * blockDim.x + threadIdx.x;   // 0..262143
    unsigned l = q >> 17;
    unsigned rem = q & 131071u;
    unsigned o = rem >> 11;
    unsigned jp = rem & 2047u;
    unsigned i = jp >> 5, ks = (jp >> 3) & 3u, pair = (jp >> 2) & 1u, t = jp & 3u;
    unsigned nt = o >> 3, g = o & 7u;
    unsigned jcol = i * 64 + ks * 16 + pair * 8 + 2 * t;
    const float* Wl = l ? W2 : W1;
    float w0 = Wl[o * 4096 + jcol];
    float w1 = Wl[o * 4096 + jcol + 1];
    unsigned e = ks * 32 + t * 8 + g;
    unsigned f = nt * 2 + pair;
    unsigned raw = e * 64 + f * 4;
    unsigned sw = raw ^ ((raw >> 3) & 0x70u);
    __half2 v = __floats2half2_rn(w0, w1);
    g_Wh[(l * 64 + i) * 2048 + (sw >> 2)] = *(unsigned*)&v;
}

__device__ __forceinline__ void mma16(float& c0, float& c1, float& c2, float& c3,
                                      unsigned a0, unsigned a1, unsigned a2, unsigned a3,
                                      unsigned b0, unsigned b1) {
    asm volatile(
        "mma.sync.aligned.m16n8k16.row.col.f32.f16.f16.f32 "
        "{%0,%1,%2,%3}, {%4,%5,%6,%7}, {%8,%9}, {%0,%1,%2,%3};"
        : "+f"(c0), "+f"(c1), "+f"(c2), "+f"(c3)
        : "r"(a0), "r"(a1), "r"(a2), "r"(a3), "r"(b0), "r"(b1));
}

__device__ __forceinline__ void cp16(void* dst_smem, const void* src) {
    unsigned d = (unsigned)__cvta_generic_to_shared(dst_smem);
    asm volatile("cp.async.cg.shared.global [%0], [%1], 16;" :: "r"(d), "l"(src) : "memory");
}

__global__ __launch_bounds__(THREADS, 2) void CIN_52553219834054_kernel(
    const float* __restrict__ x,
    const float* __restrict__ b1v, const float* __restrict__ b2v,
    const float* __restrict__ Wfc, const float* __restrict__ bfcp,
    float* __restrict__ out)
{
    extern __shared__ char smem[];
    char*    ring = smem;                                    // 4 x 8192
    __half*  X0h  = (__half*)(smem + 32768);                 // [64 f][128 p]
    __half*  Hs   = (__half*)(smem + 49152);                 // [128 p][HS_ST]
    float*   sb   = (float*)(smem + 49152 + 128 * HS_ST * 2);// b1|b2 (128)
    float*   swf  = sb + 128;                                // Wfc (128)
    float*   red  = swf + 128;                               // [2]

    const int tid  = threadIdx.x;
    const int lane = tid & 31;
    const int wid  = tid >> 5;
    const int g    = lane >> 2;
    const int t    = lane & 3;
    const int b0g  = blockIdx.x * 2;
    const int wbase = wid * 32;
    const int R0 = wbase + g, R1 = R0 + 8, R2 = R0 + 16, R3 = R0 + 24;

    // lane-constant swizzled B-word offsets (within a ks-block of 2048B)
    const unsigned c    = (unsigned)(t * 8 + g);
    const unsigned xorf = (c << 3) & 0x70u;
    const unsigned bo0 = (c * 64 +  0) ^ xorf;
    const unsigned bo1 = (c * 64 + 16) ^ xorf;
    const unsigned bo2 = (c * 64 + 32) ^ xorf;
    const unsigned bo3 = (c * 64 + 48) ^ xorf;

    // prologue prefetch: chunks 0,1,2
    #pragma unroll
    for (int pc = 0; pc < 3; pc++) {
        const unsigned* src = g_Wh + pc * 2048;
        char* buf = ring + pc * 8192;
        #pragma unroll
        for (int k = 0; k < 4; k++) {
            int widx = tid + k * 128;
            cp16(buf + widx * 16, src + widx * 4);
        }
        asm volatile("cp.async.commit_group;" ::: "memory");
    }

    // stage x -> X0h (transposed) and Hs (fp16 h0 = x)
    for (int q = tid; q < 2048; q += THREADS) {
        int bl = q >> 10, f = (q >> 4) & 63, d4 = q & 15;
        float4 v = *(const float4*)(x + (size_t)(b0g + bl) * 4096 + f * 64 + d4 * 4);
        int p = bl * 64 + d4 * 4;
        __half2 h01 = __floats2half2_rn(v.x, v.y);
        __half2 h23 = __floats2half2_rn(v.z, v.w);
        *(unsigned*)(X0h + f * 128 + p)     = *(unsigned*)&h01;
        *(unsigned*)(X0h + f * 128 + p + 2) = *(unsigned*)&h23;
        Hs[(p + 0) * HS_ST + f] = __low2half(h01);
        Hs[(p + 1) * HS_ST + f] = __high2half(h01);
        Hs[(p + 2) * HS_ST + f] = __low2half(h23);
        Hs[(p + 3) * HS_ST + f] = __high2half(h23);
    }
    if (tid < 64)  { sb[tid] = b1v[tid]; sb[64 + tid] = b2v[tid]; }
    if (tid < 128) swf[tid] = Wfc[tid];
    if (tid < 2)   red[tid] = 0.0f;
    __syncthreads();

    float pool = 0.0f;

    for (int L = 0; L < 2; L++) {
        // h fragments: hfr[row4][ks4][khalf2] as b32 (two adjacent halves)
        unsigned hfr[4][4][2];
        {
            const int rr[4] = { R0, R1, R2, R3 };
            #pragma unroll
            for (int r = 0; r < 4; r++)
                #pragma unroll
                for (int ks = 0; ks < 4; ks++) {
                    int col = ks * 16 + 2 * t;
                    hfr[r][ks][0] = *(const unsigned*)(Hs + rr[r] * HS_ST + col);
                    hfr[r][ks][1] = *(const unsigned*)(Hs + rr[r] * HS_ST + col + 8);
                }
        }

        float acc[2][8][4];
        #pragma unroll
        for (int s = 0; s < 2; s++)
            #pragma unroll
            for (int nt = 0; nt < 8; nt++)
                #pragma unroll
                for (int k = 0; k < 4; k++) acc[s][nt][k] = 0.0f;

        for (int i = 0; i < 64; i++) {
            const int gc = L * 64 + i;

            // wait for chunk gc's cp.async data (own), then publish to all
            if (gc < 126)       asm volatile("cp.async.wait_group 2;" ::: "memory");
            else if (gc == 126) asm volatile("cp.async.wait_group 1;" ::: "memory");
            else                asm volatile("cp.async.wait_group 0;" ::: "memory");
            __syncthreads();

            // prefetch chunk gc+3 (overwrites buffer of gc-1; everyone is past it)
            if (gc <= 124) {
                const unsigned* src = g_Wh + (gc + 3) * 2048;
                char* buf = ring + ((gc + 3) & 3) * 8192;
                #pragma unroll
                for (int k = 0; k < 4; k++) {
                    int widx = tid + k * 128;
                    cp16(buf + widx * 16, src + widx * 4);
                }
                asm volatile("cp.async.commit_group;" ::: "memory");
            }

            // x0 scalars for this chunk (dup to half2)
            __half2 xr0 = __half2half2(X0h[i * 128 + R0]);
            __half2 xr1 = __half2half2(X0h[i * 128 + R1]);
            __half2 xr2 = __half2half2(X0h[i * 128 + R2]);
            __half2 xr3 = __half2half2(X0h[i * 128 + R3]);

            const char* bufc = ring + (gc & 3) * 8192;

            #pragma unroll
            for (int ks = 0; ks < 4; ks++) {
                // A fragments: pa[r][khalf] = x0(row_r) * h(row_r, kslice)
                unsigned pa[4][2];
                #pragma unroll
                for (int kh = 0; kh < 2; kh++) {
                    __half2 p0 = __hmul2(xr0, *(__half2*)&hfr[0][ks][kh]);
                    __half2 p1 = __hmul2(xr1, *(__half2*)&hfr[1][ks][kh]);
                    __half2 p2 = __hmul2(xr2, *(__half2*)&hfr[2][ks][kh]);
                    __half2 p3 = __hmul2(xr3, *(__half2*)&hfr[3][ks][kh]);
                    pa[0][kh] = *(unsigned*)&p0;
                    pa[1][kh] = *(unsigned*)&p1;
                    pa[2][kh] = *(unsigned*)&p2;
                    pa[3][kh] = *(unsigned*)&p3;
                }

                const char* bk = bufc + ks * 2048;
                uint4 q0 = *(const uint4*)(bk + bo0);   // nt0,nt1
                uint4 q1 = *(const uint4*)(bk + bo1);   // nt2,nt3
                uint4 q2 = *(const uint4*)(bk + bo2);   // nt4,nt5
                uint4 q3 = *(const uint4*)(bk + bo3);   // nt6,nt7

                mma16(acc[0][0][0],acc[0][0][1],acc[0][0][2],acc[0][0][3], pa[0][0],pa[1][0],pa[0][1],pa[1][1], q0.x,q0.y);
                mma16(acc[1][0][0],acc[1][0][1],acc[1][0][2],acc[1][0][3], pa[2][0],pa[3][0],pa[2][1],pa[3][1], q0.x,q0.y);
                mma16(acc[0][1][0],acc[0][1][1],acc[0][1][2],acc[0][1][3], pa[0][0],pa[1][0],pa[0][1],pa[1][1], q0.z,q0.w);
                mma16(acc[1][1][0],acc[1][1][1],acc[1][1][2],acc[1][1][3], pa[2][0],pa[3][0],pa[2][1],pa[3][1], q0.z,q0.w);
                mma16(acc[0][2][0],acc[0][2][1],acc[0][2][2],acc[0][2][3], pa[0][0],pa[1][0],pa[0][1],pa[1][1], q1.x,q1.y);
                mma16(acc[1][2][0],acc[1][2][1],acc[1][2][2],acc[1][2][3], pa[2][0],pa[3][0],pa[2][1],pa[3][1], q1.x,q1.y);
                mma16(acc[0][3][0],acc[0][3][1],acc[0][3][2],acc[0][3][3], pa[0][0],pa[1][0],pa[0][1],pa[1][1], q1.z,q1.w);
                mma16(acc[1][3][0],acc[1][3][1],acc[1][3][2],acc[1][3][3], pa[2][0],pa[3][0],pa[2][1],pa[3][1], q1.z,q1.w);
                mma16(acc[0][4][0],acc[0][4][1],acc[0][4][2],acc[0][4][3], pa[0][0],pa[1][0],pa[0][1],pa[1][1], q2.x,q2.y);
                mma16(acc[1][4][0],acc[1][4][1],acc[1][4][2],acc[1][4][3], pa[2][0],pa[3][0],pa[2][1],pa[3][1], q2.x,q2.y);
                mma16(acc[0][5][0],acc[0][5][1],acc[0][5][2],acc[0][5][3], pa[0][0],pa[1][0],pa[0][1],pa[1][1], q2.z,q2.w);
                mma16(acc[1][5][0],acc[1][5][1],acc[1][5][2],acc[1][5][3], pa[2][0],pa[3][0],pa[2][1],pa[3][1], q2.z,q2.w);
                mma16(acc[0][6][0],acc[0][6][1],acc[0][6][2],acc[0][6][3], pa[0][0],pa[1][0],pa[0][1],pa[1][1], q3.x,q3.y);
                mma16(acc[1][6][0],acc[1][6][1],acc[1][6][2],acc[1][6][3], pa[2][0],pa[3][0],pa[2][1],pa[3][1], q3.x,q3.y);
                mma16(acc[0][7][0],acc[0][7][1],acc[0][7][2],acc[0][7][3], pa[0][0],pa[1][0],pa[0][1],pa[1][1], q3.z,q3.w);
                mma16(acc[1][7][0],acc[1][7][1],acc[1][7][2],acc[1][7][3], pa[2][0],pa[3][0],pa[2][1],pa[3][1], q3.z,q3.w);
            }
        }

        // epilogue: bias + relu, pooled FC, writeback h for layer 2
        const float* bias = sb + L * 64;
        const float* wf   = swf + L * 64;
        #pragma unroll
        for (int s = 0; s < 2; s++) {
            int rA = (s == 0) ? R0 : R2;
            int rB = rA + 8;
            #pragma unroll
            for (int nt = 0; nt < 8; nt++) {
                int n0 = nt * 8 + 2 * t;
                int n1 = n0 + 1;
                float h00 = fmaxf(acc[s][nt][0] + bias[n0], 0.0f);
                float h01 = fmaxf(acc[s][nt][1] + bias[n1], 0.0f);
                float h10 = fmaxf(acc[s][nt][2] + bias[n0], 0.0f);
                float h11 = fmaxf(acc[s][nt][3] + bias[n1], 0.0f);
                pool += (h00 + h10) * wf[n0] + (h01 + h11) * wf[n1];
                if (L == 0) {
                    Hs[rA * HS_ST + n0] = __float2half(h00);
                    Hs[rA * HS_ST + n1] = __float2half(h01);
                    Hs[rB * HS_ST + n0] = __float2half(h10);
                    Hs[rB * HS_ST + n1] = __float2half(h11);
                }
            }
        }
        __syncthreads();   // publish Hs before next layer's fragment loads
    }

    // pooled reduction: warps 0,1 -> batch 0; warps 2,3 -> batch 1
    #pragma unroll
    for (int o = 16; o; o >>= 1) pool += __shfl_xor_sync(0xFFFFFFFFu, pool, o);
    if (lane == 0) atomicAdd(&red[wid >> 1], pool);
    __syncthreads();
    if (tid < 2) out[b0g + tid] = red[tid] + bfcp[0];
}

extern "C" void kernel_launch(void* const* d_in, const int* in_sizes, int n_in,
                              void* d_out, int out_size) {
    (void)in_sizes; (void)n_in; (void)out_size;
    const float* x   = (const float*)d_in[0];
    const float* W1  = (const float*)d_in[1];
    const float* b1v = (const float*)d_in[2];
    const float* W2  = (const float*)d_in[3];
    const float* b2v = (const float*)d_in[4];
    const float* Wfc = (const float*)d_in[5];
    const float* bfc = (const float*)d_in[6];
    float* out = (float*)d_out;

    prep_kernel<<<1024, 256>>>(W1, W2);

    cudaFuncSetAttribute(CIN_52553219834054_kernel,
                         cudaFuncAttributeMaxDynamicSharedMemorySize, SMEM_BYTES);
    CIN_52553219834054_kernel<<<512, THREADS, SMEM_BYTES>>>(
        x, b1v, b2v, Wfc, bfc, out);
}

// round 13
// speedup vs baseline: 3.6329x; 1.9469x over previous
#include <cuda_runtime.h>
#include <cuda_fp16.h>
#include <cstdint>

// CIN_52553219834054 — per-(batch,d) bilinear 2-layer MLP + pooled FC via fp16 mma.sync.m16n8k16.
// Rows p = (batch_local*64 + d), 128 per CTA (2 batches). N=64 outputs. K=4096 = 64 chunks of 64.
// A[p, i*64+j] = x0[p,i]*h[p,j] synthesized in regs. B (W) pre-laid out fragment-major in gmem by
// prep kernel; main loop streams it with 8 coalesced LDG.128 per lane per chunk (no smem W path).
// Warp tiling: 2 m-halves x 2 n-halves (m64 n32 per warp) -> B traffic halved vs m32n64.

#define THREADS 128
#define HS_ST 72

__device__ __align__(16) unsigned g_Wf[524288];   // 2 layers x 64 chunks x 2 nh x 8 j8 x 32 lanes x 4 words

// prep: g_Wf[q], q = ((((l*64+i)*2+nh)*8+j8)*32+lane)*4 + wi
//   ks=j8>>1, qq=j8&1, nt=qq*2+(wi>>1), pair=wi&1, g=lane>>2, t=lane&3
//   value = half2( W[o][jcol], W[o][jcol+1] ), o = nh*32+nt*8+g, jcol = i*64+ks*16+pair*8+2t
__global__ void prep_kernel(const float* __restrict__ W1, const float* __restrict__ W2) {
    unsigned q = blockIdx.x * blockDim.x + threadIdx.x;
    if (q >= 524288u) return;
    unsigned wi   = q & 3u;
    unsigned lane = (q >> 2) & 31u;
    unsigned j8   = (q >> 7) & 7u;
    unsigned nh   = (q >> 10) & 1u;
    unsigned i    = (q >> 11) & 63u;
    unsigned l    = q >> 17;
    unsigned g = lane >> 2, t = lane & 3u;
    unsigned ks = j8 >> 1, qq = j8 & 1u;
    unsigned nt = qq * 2u + (wi >> 1), pair = wi & 1u;
    unsigned o = nh * 32u + nt * 8u + g;
    unsigned jcol = i * 64u + ks * 16u + pair * 8u + 2u * t;
    const float* Wl = l ? W2 : W1;
    __half2 v = __floats2half2_rn(Wl[o * 4096u + jcol], Wl[o * 4096u + jcol + 1u]);
    g_Wf[q] = *(unsigned*)&v;
}

__device__ __forceinline__ void mma16(float& c0, float& c1, float& c2, float& c3,
                                      unsigned a0, unsigned a1, unsigned a2, unsigned a3,
                                      unsigned b0, unsigned b1) {
    asm volatile(
        "mma.sync.aligned.m16n8k16.row.col.f32.f16.f16.f32 "
        "{%0,%1,%2,%3}, {%4,%5,%6,%7}, {%8,%9}, {%0,%1,%2,%3};"
        : "+f"(c0), "+f"(c1), "+f"(c2), "+f"(c3)
        : "r"(a0), "r"(a1), "r"(a2), "r"(a3), "r"(b0), "r"(b1));
}

__global__ __launch_bounds__(THREADS, 2) void CIN_52553219834054_kernel(
    const float* __restrict__ x,
    const float* __restrict__ b1v, const float* __restrict__ b2v,
    const float* __restrict__ Wfc, const float* __restrict__ bfcp,
    float* __restrict__ out)
{
    __shared__ __half X0p[8192];            // [i64][wm2][g8][k8]
    __shared__ __half Hs[128 * HS_ST];      // [p128][f64 (+pad)]
    __shared__ float  sb[128];              // b1 | b2
    __shared__ float  swf[128];             // Wfc
    __shared__ float  red[2];

    const int tid  = threadIdx.x;
    const int lane = tid & 31;
    const int wid  = tid >> 5;
    const int g    = lane >> 2;
    const int t    = lane & 3;
    const int wm   = wid >> 1;          // m-half (batch within CTA)
    const int nh   = wid & 1;           // n-half
    const int mb   = wm * 64;
    const int b0g  = blockIdx.x * 2;

    // stage x -> X0p (packed) and Hs (h0 = x)
    for (int q = tid; q < 2048; q += THREADS) {
        int bl = q >> 10, f = (q >> 4) & 63, d4 = q & 15;
        float4 v = *(const float4*)(x + (size_t)(b0g + bl) * 4096 + f * 64 + d4 * 4);
        int p = bl * 64 + d4 * 4;
        float vv[4] = { v.x, v.y, v.z, v.w };
        #pragma unroll
        for (int e = 0; e < 4; e++) {
            int d = d4 * 4 + e;
            __half hv = __float2half(vv[e]);
            Hs[(p + e) * HS_ST + f] = hv;
            X0p[((f * 2 + bl) * 8 + (d & 7)) * 8 + (d >> 3)] = hv;
        }
    }
    if (tid < 64)  { sb[tid] = b1v[tid]; sb[64 + tid] = b2v[tid]; }
    if (tid < 128) swf[tid] = Wfc[tid];
    if (tid < 2)   red[tid] = 0.0f;
    __syncthreads();

    // per-warp B stream base: uint4 index = gc*512 + nh*256 + j8*32 + lane
    const uint4* Wp = (const uint4*)g_Wf + (unsigned)nh * 256u + (unsigned)lane;

    #define LOADB(dst, gc) do { const uint4* _p = Wp + (unsigned)(gc) * 512u; \
        dst[0] = _p[0];   dst[1] = _p[32];  dst[2] = _p[64];  dst[3] = _p[96]; \
        dst[4] = _p[128]; dst[5] = _p[160]; dst[6] = _p[192]; dst[7] = _p[224]; } while (0)

    uint4 bA[8], bB[8];
    LOADB(bA, 0);

    float pool = 0.0f;

    for (int L = 0; L < 2; L++) {
        // h fragments: hfr[k8][ks][kh], row = mb + 8*k8 + g
        unsigned hfr[8][4][2];
        #pragma unroll
        for (int k8 = 0; k8 < 8; k8++) {
            int r = mb + 8 * k8 + g;
            #pragma unroll
            for (int ks = 0; ks < 4; ks++) {
                hfr[k8][ks][0] = *(const unsigned*)(Hs + r * HS_ST + ks * 16 + 2 * t);
                hfr[k8][ks][1] = *(const unsigned*)(Hs + r * HS_ST + ks * 16 + 2 * t + 8);
            }
        }

        float acc[4][4][4];
        #pragma unroll
        for (int s = 0; s < 4; s++)
            #pragma unroll
            for (int nt = 0; nt < 4; nt++)
                #pragma unroll
                for (int k = 0; k < 4; k++) acc[s][nt][k] = 0.0f;

        #define CONSUME(buf, ii) do { \
            uint4 xv = *(const uint4*)(X0p + (((ii) * 2 + wm) * 8 + g) * 8); \
            const __half* xh = (const __half*)&xv; \
            __half2 xd[8]; \
            _Pragma("unroll") \
            for (int k8 = 0; k8 < 8; k8++) xd[k8] = __half2half2(xh[k8]); \
            _Pragma("unroll") \
            for (int ks = 0; ks < 4; ks++) { \
                uint4 q0 = buf[ks * 2], q1 = buf[ks * 2 + 1]; \
                _Pragma("unroll") \
                for (int s = 0; s < 4; s++) { \
                    __half2 a0h = __hmul2(xd[2 * s],     *(__half2*)&hfr[2 * s][ks][0]); \
                    __half2 a1h = __hmul2(xd[2 * s + 1], *(__half2*)&hfr[2 * s + 1][ks][0]); \
                    __half2 a2h = __hmul2(xd[2 * s],     *(__half2*)&hfr[2 * s][ks][1]); \
                    __half2 a3h = __hmul2(xd[2 * s + 1], *(__half2*)&hfr[2 * s + 1][ks][1]); \
                    unsigned a0 = *(unsigned*)&a0h, a1 = *(unsigned*)&a1h; \
                    unsigned a2 = *(unsigned*)&a2h, a3 = *(unsigned*)&a3h; \
                    mma16(acc[s][0][0], acc[s][0][1], acc[s][0][2], acc[s][0][3], a0, a1, a2, a3, q0.x, q0.y); \
                    mma16(acc[s][1][0], acc[s][1][1], acc[s][1][2], acc[s][1][3], a0, a1, a2, a3, q0.z, q0.w); \
                    mma16(acc[s][2][0], acc[s][2][1], acc[s][2][2], acc[s][2][3], a0, a1, a2, a3, q1.x, q1.y); \
                    mma16(acc[s][3][0], acc[s][3][1], acc[s][3][2], acc[s][3][3], a0, a1, a2, a3, q1.z, q1.w); \
                } \
            } \
        } while (0)

        #pragma unroll 1
        for (int i = 0; i < 64; i += 2) {
            const int gc = L * 64 + i;
            LOADB(bB, gc + 1);            // gc+1 <= 127 always
            CONSUME(bA, i);
            if (gc + 2 < 128) LOADB(bA, gc + 2);
            CONSUME(bB, i + 1);
        }

        // epilogue: bias + relu, pooled FC, writeback h for layer 2
        const float* bias = sb + L * 64;
        const float* wf   = swf + L * 64;
        #pragma unroll
        for (int s = 0; s < 4; s++) {
            int r0 = mb + s * 16 + g;
            int r1 = r0 + 8;
            #pragma unroll
            for (int nt = 0; nt < 4; nt++) {
                int n0 = nh * 32 + nt * 8 + 2 * t;
                int n1 = n0 + 1;
                float h00 = fmaxf(acc[s][nt][0] + bias[n0], 0.0f);
                float h01 = fmaxf(acc[s][nt][1] + bias[n1], 0.0f);
                float h10 = fmaxf(acc[s][nt][2] + bias[n0], 0.0f);
                float h11 = fmaxf(acc[s][nt][3] + bias[n1], 0.0f);
                pool += (h00 + h10) * wf[n0] + (h01 + h11) * wf[n1];
                if (L == 0) {
                    Hs[r0 * HS_ST + n0] = __float2half(h00);
                    Hs[r0 * HS_ST + n1] = __float2half(h01);
                    Hs[r1 * HS_ST + n0] = __float2half(h10);
                    Hs[r1 * HS_ST + n1] = __float2half(h11);
                }
            }
        }
        __syncthreads();   // publish Hs before next layer's fragment loads
    }

    // pooled reduction: warps 0,1 -> batch 0; warps 2,3 -> batch 1
    #pragma unroll
    for (int o = 16; o; o >>= 1) pool += __shfl_xor_sync(0xFFFFFFFFu, pool, o);
    if (lane == 0) atomicAdd(&red[wm], pool);
    __syncthreads();
    if (tid < 2) out[b0g + tid] = red[tid] + bfcp[0];
}

extern "C" void kernel_launch(void* const* d_in, const int* in_sizes, int n_in,
                              void* d_out, int out_size) {
    (void)in_sizes; (void)n_in; (void)out_size;
    const float* x   = (const float*)d_in[0];
    const float* W1  = (const float*)d_in[1];
    const float* b1v = (const float*)d_in[2];
    const float* W2  = (const float*)d_in[3];
    const float* b2v = (const float*)d_in[4];
    const float* Wfc = (const float*)d_in[5];
    const float* bfc = (const float*)d_in[6];
    float* out = (float*)d_out;

    prep_kernel<<<2048, 256>>>(W1, W2);
    CIN_52553219834054_kernel<<<512, THREADS>>>(x, b1v, b2v, Wfc, bfc, out);
}